// round 5
// baseline (speedup 1.0000x reference)
#include <cuda_runtime.h>
#include <cuda_fp16.h>
#include <cstdint>
#include <math.h>

#define DINL __device__ __forceinline__

static constexpr int BN = 16;    // batch
static constexpr int CC = 256;   // input channels
static constexpr int CI = 128;   // inter channels
static constexpr int HW = 4096;  // pixels

// ---------------- persistent scratch (no cudaMalloc allowed) ----------------
__device__ __align__(1024) __half g_tp[2][BN][HW][CI];   // 32 MB: t (theta) / p (phi), f16

// ---------------- helpers ----------------
DINL uint32_t smem_u32(const void* p) {
    uint32_t a;
    asm("{ .reg .u64 t; cvta.to.shared.u64 t, %1; cvt.u32.u64 %0, t; }" : "=r"(a) : "l"(p));
    return a;
}
DINL void cp16(uint32_t dst, const void* src) {
    asm volatile("cp.async.cg.shared.global [%0], [%1], 16;" :: "r"(dst), "l"(src));
}
DINL void cp_commit() { asm volatile("cp.async.commit_group;" ::: "memory"); }
template <int N> DINL void cp_wait() { asm volatile("cp.async.wait_group %0;" :: "n"(N) : "memory"); }

DINL void ldsm4(uint32_t* r, uint32_t addr) {
    asm volatile("ldmatrix.sync.aligned.m8n8.x4.shared.b16 {%0,%1,%2,%3}, [%4];"
                 : "=r"(r[0]), "=r"(r[1]), "=r"(r[2]), "=r"(r[3]) : "r"(addr));
}
DINL void ldsm4t(uint32_t* r, uint32_t addr) {
    asm volatile("ldmatrix.sync.aligned.m8n8.x4.trans.shared.b16 {%0,%1,%2,%3}, [%4];"
                 : "=r"(r[0]), "=r"(r[1]), "=r"(r[2]), "=r"(r[3]) : "r"(addr));
}
// f16 inputs, f32 accum (K1)
DINL void mma_f32(float* d, const uint32_t* a, uint32_t b0, uint32_t b1) {
    asm volatile(
        "mma.sync.aligned.m16n8k16.row.col.f32.f16.f16.f32 "
        "{%0,%1,%2,%3}, {%4,%5,%6,%7}, {%8,%9}, {%0,%1,%2,%3};"
        : "+f"(d[0]), "+f"(d[1]), "+f"(d[2]), "+f"(d[3])
        : "r"(a[0]), "r"(a[1]), "r"(a[2]), "r"(a[3]), "r"(b0), "r"(b1));
}
// f16 inputs, f16 accum (K2)
DINL void mma_f16(uint32_t* d, const uint32_t* a, uint32_t b0, uint32_t b1) {
    asm volatile(
        "mma.sync.aligned.m16n8k16.row.col.f16.f16.f16.f16 "
        "{%0,%1}, {%2,%3,%4,%5}, {%6,%7}, {%0,%1};"
        : "+r"(d[0]), "+r"(d[1])
        : "r"(a[0]), "r"(a[1]), "r"(a[2]), "r"(a[3]), "r"(b0), "r"(b1));
}
DINL void sts8(uint32_t addr, uint32_t v0, uint32_t v1) {
    asm volatile("st.shared.v2.b32 [%0], {%1,%2};" :: "r"(addr), "r"(v0), "r"(v1));
}
DINL void sts2(uint32_t addr, unsigned short v) {
    asm volatile("st.shared.b16 [%0], %1;" :: "r"(addr), "h"(v));
}
DINL uint32_t h2u(__half2 h) { return *(uint32_t*)&h; }

// ---------------- K1 (fused): t/p[px][ci] = x^T w^T + bias, f16 out ----------------
// smem: W [128 ci][256 c] f16 stride 528, x chunks 2x [64 c][128 px] f16 stride 272,
// bias f32[128]. Output staged into the x-chunk area ([128 px][<=136 ci] stride 272).
static constexpr int K1_WSTR = 528;                    // 512 + 16 pad
static constexpr int K1_XOFF = 128 * K1_WSTR;          // 67584
static constexpr int K1_XSTR = 272;                    // 256 + 16 pad
static constexpr int K1_XBUF = 64 * K1_XSTR;           // 17408
static constexpr int K1_BOFF = K1_XOFF + 2 * K1_XBUF;  // 102400
static constexpr int SMEM1   = K1_BOFF + 512;          // 102912 -> 2 CTAs/SM

__global__ void __launch_bounds__(256, 2) k1_fused(
        const float* __restrict__ xg, const float* __restrict__ xq,
        const float* __restrict__ tw, const float* __restrict__ tb,
        const float* __restrict__ pw, const float* __restrict__ pb) {
    extern __shared__ char ds[];
    uint32_t sbase = smem_u32(ds);
    int tid = threadIdx.x, wid = tid >> 5, lane = tid & 31;
    int wr = wid >> 1, wc = wid & 1;           // 4 (m=ci) x 2 (n=px) warp grid
    int pt = blockIdx.x, b = blockIdx.y, which = blockIdx.z;

    const float* x = (which ? xq : xg) + (size_t)b * CC * HW + pt * 128;  // [c][HW] rows
    const float* w = which ? pw : tw;                                     // [ci][c]
    float* sbias = (float*)(ds + K1_BOFF);
    if (tid < 128) sbias[tid] = (which ? pb : tb)[tid];

    // W -> smem f16 [ci][c], stride 528
    #pragma unroll
    for (int i = 0; i < 32; i++) {
        int f = tid + i * 256;                 // 8192 float4
        int ci = f >> 6, c4 = f & 63;
        float4 v = *(const float4*)(w + ci * CC + c4 * 4);
        sts8(sbase + (uint32_t)ci * K1_WSTR + (uint32_t)c4 * 8,
             h2u(__floats2half2_rn(v.x, v.y)), h2u(__floats2half2_rn(v.z, v.w)));
    }

    float d[2][8][4];
    #pragma unroll
    for (int mt = 0; mt < 2; mt++)
        #pragma unroll
        for (int nt = 0; nt < 8; nt++)
            #pragma unroll
            for (int v = 0; v < 4; v++) d[mt][nt][v] = 0.0f;

    #pragma unroll 1
    for (int ch = 0; ch < 4; ch++) {           // k chunks of 64 channels
        uint32_t sX = sbase + K1_XOFF + (uint32_t)(ch & 1) * K1_XBUF;
        // load + convert x chunk: [64 c][128 px] f32 -> f16
        #pragma unroll
        for (int i = 0; i < 8; i++) {
            int f = tid + i * 256;             // 2048 float4
            int r = f >> 5, c4 = f & 31;
            float4 v = *(const float4*)(x + (size_t)(ch * 64 + r) * HW + c4 * 4);
            sts8(sX + (uint32_t)r * K1_XSTR + (uint32_t)c4 * 8,
                 h2u(__floats2half2_rn(v.x, v.y)), h2u(__floats2half2_rn(v.z, v.w)));
        }
        __syncthreads();

        uint32_t aA = sbase + (uint32_t)(wr * 32 + (lane & 15)) * K1_WSTR
                            + (uint32_t)(lane >> 4) * 16u + (uint32_t)ch * 128u;
        uint32_t aB = sX + (uint32_t)(lane & 15) * K1_XSTR
                         + (uint32_t)(wc * 64 + (lane >> 4) * 8) * 2u;
        #pragma unroll
        for (int kk = 0; kk < 4; kk++) {
            uint32_t a[2][4], bb[4][4];
            ldsm4(a[0], aA + kk * 32);
            ldsm4(a[1], aA + 16 * K1_WSTR + kk * 32);
            #pragma unroll
            for (int nb = 0; nb < 4; nb++)
                ldsm4t(bb[nb], aB + (uint32_t)kk * 16u * K1_XSTR + nb * 32);
            #pragma unroll
            for (int mt = 0; mt < 2; mt++)
                #pragma unroll
                for (int nb = 0; nb < 4; nb++) {
                    // trans pairing: (r0,r1) = n0-7, (r2,r3) = n8-15
                    mma_f32(d[mt][2 * nb + 0], a[mt], bb[nb][0], bb[nb][1]);
                    mma_f32(d[mt][2 * nb + 1], a[mt], bb[nb][2], bb[nb][3]);
                }
        }
        __syncthreads();
    }

    // epilogue: bias, f32->f16, transpose-stage to [px][ci] (stride 272 B)
    uint32_t so = sbase + K1_XOFF;
    #pragma unroll
    for (int mt = 0; mt < 2; mt++)
        #pragma unroll
        for (int nt = 0; nt < 8; nt++) {
            int row = wr * 32 + mt * 16 + (lane >> 2);     // ci
            int px  = wc * 64 + nt * 8 + 2 * (lane & 3);   // px (2 adjacent)
            float b0 = sbias[row], b1 = sbias[row + 8];
            sts2(so + (uint32_t)px * K1_XSTR + row * 2,
                 __half_as_ushort(__float2half_rn(d[mt][nt][0] + b0)));
            sts2(so + (uint32_t)(px + 1) * K1_XSTR + row * 2,
                 __half_as_ushort(__float2half_rn(d[mt][nt][1] + b0)));
            sts2(so + (uint32_t)px * K1_XSTR + (row + 8) * 2,
                 __half_as_ushort(__float2half_rn(d[mt][nt][2] + b1)));
            sts2(so + (uint32_t)(px + 1) * K1_XSTR + (row + 8) * 2,
                 __half_as_ushort(__float2half_rn(d[mt][nt][3] + b1)));
        }
    __syncthreads();

    uint32_t* go = (uint32_t*)&g_tp[which][b][pt * 128][0];
    const uint32_t* sou = (const uint32_t*)(ds + K1_XOFF);
    #pragma unroll
    for (int i = 0; i < 32; i++) {
        int idx = tid + i * 256;               // 8192 u32
        int row = idx >> 6, col = idx & 63;
        go[row * 64 + col] = sou[row * 68 + col];   // 272 B / 4 = 68 u32 stride
    }
}

// ---------------- K2: f = t p^T / 4096, fused row-max + sigmoid ----------------
static constexpr int K2_STR = 272;                  // 256 + 16 pad
static constexpr int K2_B0  = 128 * K2_STR;         // 34816
static constexpr int K2_B1  = 2 * 128 * K2_STR;     // 69632
static constexpr int K2_RED = 3 * 128 * K2_STR;     // 104448
static constexpr int SMEM2  = K2_RED + 1024;        // 105472 -> 2 CTAs/SM

DINL void load_tile272(uint32_t sbase, const __half* g, int tid) {
    const char* gb = (const char*)g;
    #pragma unroll
    for (int i = 0; i < 8; ++i) {
        int k = tid + i * 256;                 // 2048 x 16B segs
        cp16(sbase + (uint32_t)(k >> 4) * K2_STR + (uint32_t)(k & 15) * 16u,
             gb + (size_t)k * 16);
    }
}

__global__ void __launch_bounds__(256, 2) k2_attn(float* __restrict__ out) {
    extern __shared__ char ds[];
    uint32_t sbase = smem_u32(ds);
    int tid = threadIdx.x, wid = tid >> 5, lane = tid & 31;
    int wr = wid >> 1, wc = wid & 1;
    int it = blockIdx.x, b = blockIdx.y;

    const __half* ga = &g_tp[0][b][it * 128][0];   // t rows [128 i][128 c]
    const __half* gp = &g_tp[1][b][0][0];          // p rows [4096 j][128 c]

    load_tile272(sbase, ga, tid);
    load_tile272(sbase + K2_B0, gp, tid);
    cp_commit();                                   // group: A + B0
    load_tile272(sbase + K2_B1, gp + (size_t)128 * CI, tid);
    cp_commit();                                   // group: B1

    uint32_t rmax2[2][2] = {{0xFC00FC00u, 0xFC00FC00u}, {0xFC00FC00u, 0xFC00FC00u}};

    uint32_t aA = sbase + (uint32_t)(wr * 32 + (lane & 15)) * K2_STR + (uint32_t)(lane >> 4) * 16u;

    #pragma unroll 1
    for (int n = 0; n < 32; ++n) {
        cp_wait<1>();                 // chunk n resident (one group pending)
        __syncthreads();

        uint32_t sB = sbase + ((n & 1) ? K2_B1 : K2_B0);
        uint32_t aB = sB + (uint32_t)(wc * 64 + (lane & 15)) * K2_STR + (uint32_t)(lane >> 4) * 16u;

        uint32_t d[2][8][2];
        #pragma unroll
        for (int mt = 0; mt < 2; mt++)
            #pragma unroll
            for (int nt = 0; nt < 8; nt++) { d[mt][nt][0] = 0u; d[mt][nt][1] = 0u; }

        #pragma unroll
        for (int kk = 0; kk < 8; kk++) {
            uint32_t a[2][4], bb[4][4];
            ldsm4(a[0], aA + kk * 32);
            ldsm4(a[1], aA + 16 * K2_STR + kk * 32);
            #pragma unroll
            for (int nb = 0; nb < 4; nb++) ldsm4(bb[nb], aB + nb * 16 * K2_STR + kk * 32);
            #pragma unroll
            for (int mt = 0; mt < 2; mt++)
                #pragma unroll
                for (int nb = 0; nb < 4; nb++) {
                    // non-trans [n][k] pairing: (r0,r2) = n0-7, (r1,r3) = n8-15
                    mma_f16(d[mt][2 * nb + 0], a[mt], bb[nb][0], bb[nb][2]);
                    mma_f16(d[mt][2 * nb + 1], a[mt], bb[nb][1], bb[nb][3]);
                }
        }

        // fold into running per-row max (packed half2: 2 adjacent j cols, same row)
        #pragma unroll
        for (int mt = 0; mt < 2; mt++)
            #pragma unroll
            for (int nt = 0; nt < 8; nt++) {
                rmax2[mt][0] = h2u(__hmax2(*(__half2*)&rmax2[mt][0], *(__half2*)&d[mt][nt][0]));
                rmax2[mt][1] = h2u(__hmax2(*(__half2*)&rmax2[mt][1], *(__half2*)&d[mt][nt][1]));
            }

        __syncthreads();              // all warps done reading buf n&1
        if (n + 2 < 32)
            load_tile272(sB, gp + (size_t)(n + 2) * 128 * CI, tid);
        cp_commit();                  // keep group count in lockstep
    }

    // cross-lane (j direction) reduce: quad shfl, then across warp columns via smem
    float* red = (float*)(ds + K2_RED);   // [128][2]
    #pragma unroll
    for (int mt = 0; mt < 2; mt++)
        #pragma unroll
        for (int h = 0; h < 2; h++) {
            __half2 p = *(__half2*)&rmax2[mt][h];
            float v = fmaxf(__low2float(p), __high2float(p));
            v = fmaxf(v, __shfl_xor_sync(0xffffffffu, v, 1));
            v = fmaxf(v, __shfl_xor_sync(0xffffffffu, v, 2));
            if ((lane & 3) == 0) {
                int i_loc = wr * 32 + mt * 16 + (lane >> 2) + 8 * h;
                red[i_loc * 2 + wc] = v;
            }
        }
    __syncthreads();

    if (tid < 128) {
        float m = fmaxf(red[tid * 2], red[tid * 2 + 1]) * (1.0f / 4096.0f);
        out[(size_t)b * HW + it * 128 + tid] = 1.0f / (1.0f + expf(-m));
    }
}

// ---------------- launch ----------------
extern "C" void kernel_launch(void* const* d_in, const int* in_sizes, int n_in,
                              void* d_out, int out_size) {
    const float* xg = (const float*)d_in[0];
    const float* xq = (const float*)d_in[1];
    const float* tw = (const float*)d_in[2];
    const float* tb = (const float*)d_in[3];
    const float* pw = (const float*)d_in[4];
    const float* pb = (const float*)d_in[5];
    float* out = (float*)d_out;

    cudaFuncSetAttribute(k1_fused, cudaFuncAttributeMaxDynamicSharedMemorySize, SMEM1);
    cudaFuncSetAttribute(k2_attn,  cudaFuncAttributeMaxDynamicSharedMemorySize, SMEM2);

    k1_fused<<<dim3(HW / 128, BN, 2), 256, SMEM1>>>(xg, xq, tw, tb, pw, pb);
    k2_attn<<<dim3(HW / 128, BN), 256, SMEM2>>>(out);
}

// round 6
// speedup vs baseline: 1.0060x; 1.0060x over previous
#include <cuda_runtime.h>
#include <cuda_fp16.h>
#include <cstdint>
#include <math.h>

#define DINL __device__ __forceinline__

static constexpr int BN = 16;    // batch
static constexpr int CC = 256;   // input channels
static constexpr int CI = 128;   // inter channels
static constexpr int HW = 4096;  // pixels

// ---------------- persistent scratch (no cudaMalloc allowed) ----------------
__device__ __align__(1024) __half g_tp[2][BN][HW][CI];   // 32 MB: t (theta) / p (phi), f16

// ---------------- helpers ----------------
DINL uint32_t smem_u32(const void* p) {
    uint32_t a;
    asm("{ .reg .u64 t; cvta.to.shared.u64 t, %1; cvt.u32.u64 %0, t; }" : "=r"(a) : "l"(p));
    return a;
}
DINL void cp16(uint32_t dst, const void* src) {
    asm volatile("cp.async.cg.shared.global [%0], [%1], 16;" :: "r"(dst), "l"(src));
}
DINL void cp_commit() { asm volatile("cp.async.commit_group;" ::: "memory"); }
template <int N> DINL void cp_wait() { asm volatile("cp.async.wait_group %0;" :: "n"(N) : "memory"); }

DINL void ldsm4(uint32_t* r, uint32_t addr) {
    asm volatile("ldmatrix.sync.aligned.m8n8.x4.shared.b16 {%0,%1,%2,%3}, [%4];"
                 : "=r"(r[0]), "=r"(r[1]), "=r"(r[2]), "=r"(r[3]) : "r"(addr));
}
DINL void ldsm4t(uint32_t* r, uint32_t addr) {
    asm volatile("ldmatrix.sync.aligned.m8n8.x4.trans.shared.b16 {%0,%1,%2,%3}, [%4];"
                 : "=r"(r[0]), "=r"(r[1]), "=r"(r[2]), "=r"(r[3]) : "r"(addr));
}
// f16 inputs, f32 accum (K1)
DINL void mma_f32(float* d, const uint32_t* a, uint32_t b0, uint32_t b1) {
    asm volatile(
        "mma.sync.aligned.m16n8k16.row.col.f32.f16.f16.f32 "
        "{%0,%1,%2,%3}, {%4,%5,%6,%7}, {%8,%9}, {%0,%1,%2,%3};"
        : "+f"(d[0]), "+f"(d[1]), "+f"(d[2]), "+f"(d[3])
        : "r"(a[0]), "r"(a[1]), "r"(a[2]), "r"(a[3]), "r"(b0), "r"(b1));
}
// f16 inputs, f16 accum (K2)
DINL void mma_f16(uint32_t* d, const uint32_t* a, uint32_t b0, uint32_t b1) {
    asm volatile(
        "mma.sync.aligned.m16n8k16.row.col.f16.f16.f16.f16 "
        "{%0,%1}, {%2,%3,%4,%5}, {%6,%7}, {%0,%1};"
        : "+r"(d[0]), "+r"(d[1])
        : "r"(a[0]), "r"(a[1]), "r"(a[2]), "r"(a[3]), "r"(b0), "r"(b1));
}
DINL void sts8(uint32_t addr, uint32_t v0, uint32_t v1) {
    asm volatile("st.shared.v2.b32 [%0], {%1,%2};" :: "r"(addr), "r"(v0), "r"(v1));
}
DINL void sts2(uint32_t addr, unsigned short v) {
    asm volatile("st.shared.b16 [%0], %1;" :: "r"(addr), "h"(v));
}
DINL uint32_t h2u(__half2 h) { return *(uint32_t*)&h; }

// ---------------- K1 (fused): t/p[px][ci] = x^T w^T + bias, f16 out ----------------
// smem: W [128 ci][256 c] f16 stride 528, x chunks 2x [64 c][128 px] f16 stride 272,
// bias f32[128]. Output staged into the x-chunk area ([128 px][<=136 ci] stride 272).
static constexpr int K1_WSTR = 528;                    // 512 + 16 pad
static constexpr int K1_XOFF = 128 * K1_WSTR;          // 67584
static constexpr int K1_XSTR = 272;                    // 256 + 16 pad
static constexpr int K1_XBUF = 64 * K1_XSTR;           // 17408
static constexpr int K1_BOFF = K1_XOFF + 2 * K1_XBUF;  // 102400
static constexpr int SMEM1   = K1_BOFF + 512;          // 102912 -> 2 CTAs/SM

__global__ void __launch_bounds__(256, 2) k1_fused(
        const float* __restrict__ xg, const float* __restrict__ xq,
        const float* __restrict__ tw, const float* __restrict__ tb,
        const float* __restrict__ pw, const float* __restrict__ pb) {
    extern __shared__ char ds[];
    uint32_t sbase = smem_u32(ds);
    int tid = threadIdx.x, wid = tid >> 5, lane = tid & 31;
    int wr = wid >> 1, wc = wid & 1;           // 4 (m=ci) x 2 (n=px) warp grid
    int pt = blockIdx.x, b = blockIdx.y, which = blockIdx.z;

    const float* x = (which ? xq : xg) + (size_t)b * CC * HW + pt * 128;  // [c][HW] rows
    const float* w = which ? pw : tw;                                     // [ci][c]
    float* sbias = (float*)(ds + K1_BOFF);
    if (tid < 128) sbias[tid] = (which ? pb : tb)[tid];

    // W -> smem f16 [ci][c], stride 528
    #pragma unroll
    for (int i = 0; i < 32; i++) {
        int f = tid + i * 256;                 // 8192 float4
        int ci = f >> 6, c4 = f & 63;
        float4 v = *(const float4*)(w + ci * CC + c4 * 4);
        sts8(sbase + (uint32_t)ci * K1_WSTR + (uint32_t)c4 * 8,
             h2u(__floats2half2_rn(v.x, v.y)), h2u(__floats2half2_rn(v.z, v.w)));
    }

    float d[2][8][4];
    #pragma unroll
    for (int mt = 0; mt < 2; mt++)
        #pragma unroll
        for (int nt = 0; nt < 8; nt++)
            #pragma unroll
            for (int v = 0; v < 4; v++) d[mt][nt][v] = 0.0f;

    #pragma unroll 1
    for (int ch = 0; ch < 4; ch++) {           // k chunks of 64 channels
        uint32_t sX = sbase + K1_XOFF + (uint32_t)(ch & 1) * K1_XBUF;
        // load + convert x chunk: [64 c][128 px] f32 -> f16
        #pragma unroll
        for (int i = 0; i < 8; i++) {
            int f = tid + i * 256;             // 2048 float4
            int r = f >> 5, c4 = f & 31;
            float4 v = *(const float4*)(x + (size_t)(ch * 64 + r) * HW + c4 * 4);
            sts8(sX + (uint32_t)r * K1_XSTR + (uint32_t)c4 * 8,
                 h2u(__floats2half2_rn(v.x, v.y)), h2u(__floats2half2_rn(v.z, v.w)));
        }
        __syncthreads();

        uint32_t aA = sbase + (uint32_t)(wr * 32 + (lane & 15)) * K1_WSTR
                            + (uint32_t)(lane >> 4) * 16u + (uint32_t)ch * 128u;
        uint32_t aB = sX + (uint32_t)(lane & 15) * K1_XSTR
                         + (uint32_t)(wc * 64 + (lane >> 4) * 8) * 2u;
        #pragma unroll
        for (int kk = 0; kk < 4; kk++) {
            uint32_t a[2][4], bb[4][4];
            ldsm4(a[0], aA + kk * 32);
            ldsm4(a[1], aA + 16 * K1_WSTR + kk * 32);
            #pragma unroll
            for (int nb = 0; nb < 4; nb++)
                ldsm4t(bb[nb], aB + (uint32_t)kk * 16u * K1_XSTR + nb * 32);
            #pragma unroll
            for (int mt = 0; mt < 2; mt++)
                #pragma unroll
                for (int nb = 0; nb < 4; nb++) {
                    // trans pairing: (r0,r1) = n0-7, (r2,r3) = n8-15
                    mma_f32(d[mt][2 * nb + 0], a[mt], bb[nb][0], bb[nb][1]);
                    mma_f32(d[mt][2 * nb + 1], a[mt], bb[nb][2], bb[nb][3]);
                }
        }
        __syncthreads();
    }

    // epilogue: bias, f32->f16, transpose-stage to [px][ci] (stride 272 B)
    uint32_t so = sbase + K1_XOFF;
    #pragma unroll
    for (int mt = 0; mt < 2; mt++)
        #pragma unroll
        for (int nt = 0; nt < 8; nt++) {
            int row = wr * 32 + mt * 16 + (lane >> 2);     // ci
            int px  = wc * 64 + nt * 8 + 2 * (lane & 3);   // px (2 adjacent)
            float b0 = sbias[row], b1 = sbias[row + 8];
            sts2(so + (uint32_t)px * K1_XSTR + row * 2,
                 __half_as_ushort(__float2half_rn(d[mt][nt][0] + b0)));
            sts2(so + (uint32_t)(px + 1) * K1_XSTR + row * 2,
                 __half_as_ushort(__float2half_rn(d[mt][nt][1] + b0)));
            sts2(so + (uint32_t)px * K1_XSTR + (row + 8) * 2,
                 __half_as_ushort(__float2half_rn(d[mt][nt][2] + b1)));
            sts2(so + (uint32_t)(px + 1) * K1_XSTR + (row + 8) * 2,
                 __half_as_ushort(__float2half_rn(d[mt][nt][3] + b1)));
        }
    __syncthreads();

    uint32_t* go = (uint32_t*)&g_tp[which][b][pt * 128][0];
    const uint32_t* sou = (const uint32_t*)(ds + K1_XOFF);
    #pragma unroll
    for (int i = 0; i < 32; i++) {
        int idx = tid + i * 256;               // 8192 u32
        int row = idx >> 6, col = idx & 63;
        go[row * 64 + col] = sou[row * 68 + col];   // 272 B / 4 = 68 u32 stride
    }
}

// ---------------- K2: f = t p^T / 4096, fused row-max + sigmoid ----------------
static constexpr int K2_STR = 272;                  // 256 + 16 pad
static constexpr int K2_B0  = 128 * K2_STR;         // 34816
static constexpr int K2_B1  = 2 * 128 * K2_STR;     // 69632
static constexpr int K2_RED = 3 * 128 * K2_STR;     // 104448
static constexpr int SMEM2  = K2_RED + 1024;        // 105472 -> 2 CTAs/SM

DINL void load_tile272(uint32_t sbase, const __half* g, int tid) {
    const char* gb = (const char*)g;
    #pragma unroll
    for (int i = 0; i < 8; ++i) {
        int k = tid + i * 256;                 // 2048 x 16B segs
        cp16(sbase + (uint32_t)(k >> 4) * K2_STR + (uint32_t)(k & 15) * 16u,
             gb + (size_t)k * 16);
    }
}

__global__ void __launch_bounds__(256, 2) k2_attn(float* __restrict__ out) {
    extern __shared__ char ds[];
    uint32_t sbase = smem_u32(ds);
    int tid = threadIdx.x, wid = tid >> 5, lane = tid & 31;
    int wr = wid >> 1, wc = wid & 1;
    int it = blockIdx.x, b = blockIdx.y;

    const __half* ga = &g_tp[0][b][it * 128][0];   // t rows [128 i][128 c]
    const __half* gp = &g_tp[1][b][0][0];          // p rows [4096 j][128 c]

    load_tile272(sbase, ga, tid);
    load_tile272(sbase + K2_B0, gp, tid);
    cp_commit();                                   // group: A + B0
    load_tile272(sbase + K2_B1, gp + (size_t)128 * CI, tid);
    cp_commit();                                   // group: B1

    uint32_t rmax2[2][2] = {{0xFC00FC00u, 0xFC00FC00u}, {0xFC00FC00u, 0xFC00FC00u}};

    uint32_t aA = sbase + (uint32_t)(wr * 32 + (lane & 15)) * K2_STR + (uint32_t)(lane >> 4) * 16u;

    #pragma unroll 1
    for (int n = 0; n < 32; ++n) {
        cp_wait<1>();                 // chunk n resident (one group pending)
        __syncthreads();

        uint32_t sB = sbase + ((n & 1) ? K2_B1 : K2_B0);
        uint32_t aB = sB + (uint32_t)(wc * 64 + (lane & 15)) * K2_STR + (uint32_t)(lane >> 4) * 16u;

        uint32_t d[2][8][2];
        #pragma unroll
        for (int mt = 0; mt < 2; mt++)
            #pragma unroll
            for (int nt = 0; nt < 8; nt++) { d[mt][nt][0] = 0u; d[mt][nt][1] = 0u; }

        #pragma unroll
        for (int kk = 0; kk < 8; kk++) {
            uint32_t a[2][4], bb[4][4];
            ldsm4(a[0], aA + kk * 32);
            ldsm4(a[1], aA + 16 * K2_STR + kk * 32);
            #pragma unroll
            for (int nb = 0; nb < 4; nb++) ldsm4(bb[nb], aB + nb * 16 * K2_STR + kk * 32);
            #pragma unroll
            for (int mt = 0; mt < 2; mt++)
                #pragma unroll
                for (int nb = 0; nb < 4; nb++) {
                    // non-trans [n][k] pairing: (r0,r2) = n0-7, (r1,r3) = n8-15
                    mma_f16(d[mt][2 * nb + 0], a[mt], bb[nb][0], bb[nb][2]);
                    mma_f16(d[mt][2 * nb + 1], a[mt], bb[nb][1], bb[nb][3]);
                }
        }

        // fold into running per-row max (packed half2: 2 adjacent j cols, same row)
        #pragma unroll
        for (int mt = 0; mt < 2; mt++)
            #pragma unroll
            for (int nt = 0; nt < 8; nt++) {
                rmax2[mt][0] = h2u(__hmax2(*(__half2*)&rmax2[mt][0], *(__half2*)&d[mt][nt][0]));
                rmax2[mt][1] = h2u(__hmax2(*(__half2*)&rmax2[mt][1], *(__half2*)&d[mt][nt][1]));
            }

        __syncthreads();              // all warps done reading buf n&1
        if (n + 2 < 32)
            load_tile272(sB, gp + (size_t)(n + 2) * 128 * CI, tid);
        cp_commit();                  // keep group count in lockstep
    }

    // cross-lane (j direction) reduce: quad shfl, then across warp columns via smem
    float* red = (float*)(ds + K2_RED);   // [128][2]
    #pragma unroll
    for (int mt = 0; mt < 2; mt++)
        #pragma unroll
        for (int h = 0; h < 2; h++) {
            __half2 p = *(__half2*)&rmax2[mt][h];
            float v = fmaxf(__low2float(p), __high2float(p));
            v = fmaxf(v, __shfl_xor_sync(0xffffffffu, v, 1));
            v = fmaxf(v, __shfl_xor_sync(0xffffffffu, v, 2));
            if ((lane & 3) == 0) {
                int i_loc = wr * 32 + mt * 16 + (lane >> 2) + 8 * h;
                red[i_loc * 2 + wc] = v;
            }
        }
    __syncthreads();

    if (tid < 128) {
        float m = fmaxf(red[tid * 2], red[tid * 2 + 1]) * (1.0f / 4096.0f);
        out[(size_t)b * HW + it * 128 + tid] = 1.0f / (1.0f + expf(-m));
    }
}

// ---------------- launch ----------------
extern "C" void kernel_launch(void* const* d_in, const int* in_sizes, int n_in,
                              void* d_out, int out_size) {
    const float* xg = (const float*)d_in[0];
    const float* xq = (const float*)d_in[1];
    const float* tw = (const float*)d_in[2];
    const float* tb = (const float*)d_in[3];
    const float* pw = (const float*)d_in[4];
    const float* pb = (const float*)d_in[5];
    float* out = (float*)d_out;

    cudaFuncSetAttribute(k1_fused, cudaFuncAttributeMaxDynamicSharedMemorySize, SMEM1);
    cudaFuncSetAttribute(k2_attn,  cudaFuncAttributeMaxDynamicSharedMemorySize, SMEM2);

    k1_fused<<<dim3(HW / 128, BN, 2), 256, SMEM1>>>(xg, xq, tw, tb, pw, pb);
    k2_attn<<<dim3(HW / 128, BN), 256, SMEM2>>>(out);
}